// round 3
// baseline (speedup 1.0000x reference)
#include <cuda_runtime.h>
#include <math.h>
#include <stdint.h>
#include <stddef.h>

// ---------------- problem dims (fixed) ----------------
#define BB   8
#define LL   2048
#define CIN  32
#define DMODEL 512
#define DFF  2048
#define NH   8
#define HD   64
#define NE   2
#define UU   24            // u = U_part = 3*ceil(ln(2048)) = 24
#define MROWS (BB*LL)      // 16384

// ---------------- scratch (static device globals; no allocation) ----------------
__device__ float g_xln [MROWS*CIN];
__device__ float g_h   [(size_t)MROWS*DMODEL];
__device__ float g_q   [(size_t)MROWS*DMODEL];
__device__ float g_k   [(size_t)MROWS*DMODEL];
__device__ float g_v   [(size_t)MROWS*DMODEL];
__device__ float g_attn[(size_t)MROWS*DMODEL];
__device__ float g_ffn [(size_t)MROWS*DFF];
__device__ float g_M   [BB*NH*LL];
__device__ int   g_samp[LL*UU];
__device__ int   g_idxtop[BB*NH*UU];
__device__ float g_vmean[BB*NH*HD];
__device__ float g_upd [BB*NH*UU*HD];
__device__ float g_last[BB*DMODEL];

// ---------------- threefry2x32 (matches JAX) ----------------
__device__ __forceinline__ void tf2x32(uint32_t k0, uint32_t k1,
                                       uint32_t x0, uint32_t x1,
                                       uint32_t& o0, uint32_t& o1) {
    uint32_t ks2 = k0 ^ k1 ^ 0x1BD11BDAu;
    uint32_t v0 = x0 + k0, v1 = x1 + k1;
#define TF_RND(r) { v0 += v1; v1 = (v1 << (r)) | (v1 >> (32 - (r))); v1 ^= v0; }
    TF_RND(13) TF_RND(15) TF_RND(26) TF_RND(6)   v0 += k1;  v1 += ks2 + 1u;
    TF_RND(17) TF_RND(29) TF_RND(16) TF_RND(24)  v0 += ks2; v1 += k0 + 2u;
    TF_RND(13) TF_RND(15) TF_RND(26) TF_RND(6)   v0 += k0;  v1 += k1 + 3u;
    TF_RND(17) TF_RND(29) TF_RND(16) TF_RND(24)  v0 += k1;  v1 += ks2 + 4u;
    TF_RND(13) TF_RND(15) TF_RND(26) TF_RND(6)   v0 += ks2; v1 += k0 + 5u;
#undef TF_RND
    o0 = v0; o1 = v1;
}

// idx_sample = randint(fold_in(key(42), layer), (2048,24), 0, 2048)
// under jax_threefry_partitionable=True (modern default):
//   fold_in:  key2 = tf_block((0,42), (0, layer))             (unchanged)
//   split:    k_i  = tf_block(key, hi=0, lo=i)  -> k2 = block(key2, 0, 1)
//   bits[j]   = o0 ^ o1 of tf_block(k2, hi=0, lo=j)           (64-bit iota split)
//   idx       = bits mod 2048  (multiplier term = 0 since 2048 | 2^16)
__global__ void sample_kernel(int layer) {
    int j = blockIdx.x * blockDim.x + threadIdx.x;
    if (j >= LL * UU) return;
    uint32_t a0, a1;
    tf2x32(0u, 42u, 0u, (uint32_t)layer, a0, a1);   // fold_in
    uint32_t k2a, k2b;
    tf2x32(a0, a1, 0u, 1u, k2a, k2b);               // split -> second key
    uint32_t o0, o1;
    tf2x32(k2a, k2b, 0u, (uint32_t)j, o0, o1);      // partitionable random_bits
    g_samp[j] = (int)((o0 ^ o1) & 2047u);
}

// ---------------- input layernorm over C_IN=32 (one warp per row) ----------------
__global__ void ln32_kernel(const float* __restrict__ x,
                            const float* __restrict__ g, const float* __restrict__ b) {
    int row  = blockIdx.x * 8 + (threadIdx.x >> 5);
    int lane = threadIdx.x & 31;
    float v = x[(size_t)row * CIN + lane];
    float s = v;
    #pragma unroll
    for (int o = 16; o; o >>= 1) s += __shfl_xor_sync(~0u, s, o);
    float m = s * (1.f / 32.f);
    float d = v - m;
    float ss = d * d;
    #pragma unroll
    for (int o = 16; o; o >>= 1) ss += __shfl_xor_sync(~0u, ss, o);
    float var = ss * (1.f / 32.f);
    float r = rsqrtf(var + 1e-5f);
    g_xln[(size_t)row * CIN + lane] = d * r * g[lane] + b[lane];
}

// ---------------- token conv (wrap pad, k=3) + pos emb + time proj ----------------
__global__ void embed_kernel(const float* __restrict__ tfeat,
                             const float* __restrict__ Wtok,   // [3][32][512]
                             const float* __restrict__ Wtime,  // [512][4]
                             const float* __restrict__ btime) {
    int bl = blockIdx.x;
    int l = bl & (LL - 1);
    int b = bl >> 11;
    __shared__ float xs[96];
    __shared__ float tf[4];
    int tid = threadIdx.x; // 128
    if (tid < 96) {
        int w = tid / 32, c = tid % 32;
        int lsrc = (l - 1 + w + LL) & (LL - 1);   // wrap pad
        xs[tid] = g_xln[((size_t)b * LL + lsrc) * CIN + c];
    }
    if (tid < 4) tf[tid] = tfeat[((size_t)b * LL + l) * 4 + tid];
    __syncthreads();
    for (int m = tid; m < DMODEL; m += 128) {
        float acc = btime[m];
        #pragma unroll 8
        for (int wc = 0; wc < 96; wc++) acc += xs[wc] * Wtok[wc * DMODEL + m];
        #pragma unroll
        for (int t = 0; t < 4; t++) acc += tf[t] * Wtime[m * 4 + t];
        // positional embedding (double precision internally, as numpy does)
        int i2 = m & ~1;
        double dv  = exp(-(double)i2 * (9.210340371976184 / 512.0)); // ln(1e4)/512
        double arg = (double)l * dv;
        float pe = (m & 1) ? (float)cos(arg) : (float)sin(arg);
        g_h[((size_t)b * LL + l) * DMODEL + m] = acc + pe;
    }
}

// ---------------- SGEMM: C[M,N] = A[M,K] @ W[N,K]^T + bias (+res) (relu?) ----------
// BM=BN=128, BK=8, 256 threads, 8x8 microtile, register prefetch of next k-slab.
template<int RELU, int RES>
__global__ __launch_bounds__(256)
void sgemm_kernel(const float* __restrict__ A, const float* __restrict__ W,
                  const float* __restrict__ bias, const float* __restrict__ res,
                  float* __restrict__ C, int M, int N, int K) {
    __shared__ float As[8][128];
    __shared__ float Ws[8][128];
    int tid = threadIdx.x;
    int tx = tid & 15, ty = tid >> 4;
    size_t bm = blockIdx.y, bn = blockIdx.x;
    int lr = tid >> 1;
    int lc = (tid & 1) * 4;
    const float* Ag = A + (bm * 128 + lr) * (size_t)K + lc;
    const float* Wg = W + (bn * 128 + lr) * (size_t)K + lc;
    float4 apre = *(const float4*)Ag;
    float4 wpre = *(const float4*)Wg;
    float acc[8][8];
    #pragma unroll
    for (int i = 0; i < 8; i++)
        #pragma unroll
        for (int j = 0; j < 8; j++) acc[i][j] = 0.f;

    for (int k0 = 0; k0 < K; k0 += 8) {
        As[lc+0][lr] = apre.x; As[lc+1][lr] = apre.y; As[lc+2][lr] = apre.z; As[lc+3][lr] = apre.w;
        Ws[lc+0][lr] = wpre.x; Ws[lc+1][lr] = wpre.y; Ws[lc+2][lr] = wpre.z; Ws[lc+3][lr] = wpre.w;
        __syncthreads();
        if (k0 + 8 < K) {
            apre = *(const float4*)(Ag + k0 + 8);
            wpre = *(const float4*)(Wg + k0 + 8);
        }
        #pragma unroll
        for (int kk = 0; kk < 8; kk++) {
            float a[8], bv[8];
            #pragma unroll
            for (int i = 0; i < 8; i++) a[i]  = As[kk][ty + 16 * i];
            #pragma unroll
            for (int j = 0; j < 8; j++) bv[j] = Ws[kk][tx + 16 * j];
            #pragma unroll
            for (int i = 0; i < 8; i++)
                #pragma unroll
                for (int j = 0; j < 8; j++) acc[i][j] += a[i] * bv[j];
        }
        __syncthreads();
    }
    #pragma unroll
    for (int i = 0; i < 8; i++) {
        size_t m = bm * 128 + ty + 16 * i;
        #pragma unroll
        for (int j = 0; j < 8; j++) {
            size_t n = bn * 128 + tx + 16 * j;
            float vv = acc[i][j] + bias[n];
            if (RES)  vv += res[m * (size_t)N + n];
            if (RELU) vv = fmaxf(vv, 0.f);
            C[m * (size_t)N + n] = vv;
        }
    }
}

// ---------------- M scores: M[b,h,l] = max_s(q.k_s) - sum_s(q.k_s)/L ----------------
__global__ void mscore_kernel() {
    int wid  = (blockIdx.x * blockDim.x + threadIdx.x) >> 5;
    int lane = threadIdx.x & 31;
    if (wid >= BB * NH * LL) return;
    int l = wid & (LL - 1);
    int h = (wid >> 11) & (NH - 1);
    int b = wid >> 14;
    const float* qr = g_q + (((size_t)b * LL + l) * NH + h) * HD;
    float q0 = qr[lane * 2], q1 = qr[lane * 2 + 1];
    float mx = -INFINITY, sm = 0.f;
    #pragma unroll 4
    for (int s = 0; s < UU; s++) {
        int ks = g_samp[l * UU + s];
        const float* kr = g_k + (((size_t)b * LL + ks) * NH + h) * HD;
        float v = q0 * kr[lane * 2] + q1 * kr[lane * 2 + 1];
        #pragma unroll
        for (int o = 16; o; o >>= 1) v += __shfl_xor_sync(~0u, v, o);
        mx = fmaxf(mx, v);
        sm += v;
    }
    if (lane == 0)
        g_M[((size_t)(b * NH + h)) * LL + l] = mx - sm * (1.0f / (float)LL);
}

// ---------------- top-24 per (b,h) with JAX tie semantics (smaller idx wins) -------
__global__ void topk_kernel() {
    int bh = blockIdx.x;     // 64
    int tid = threadIdx.x;   // 256
    __shared__ float sv[LL];
    __shared__ float rv[256];
    __shared__ int   ri[256];
    for (int i = tid; i < LL; i += 256) sv[i] = g_M[(size_t)bh * LL + i];
    __syncthreads();
    for (int t = 0; t < UU; t++) {
        float bvv = -INFINITY; int bi = LL;
        for (int i = tid; i < LL; i += 256) {
            float v = sv[i];
            if (v > bvv || (v == bvv && i < bi)) { bvv = v; bi = i; }
        }
        rv[tid] = bvv; ri[tid] = bi;
        __syncthreads();
        for (int s = 128; s > 0; s >>= 1) {
            if (tid < s) {
                float v2 = rv[tid + s]; int i2 = ri[tid + s];
                if (v2 > rv[tid] || (v2 == rv[tid] && i2 < ri[tid])) { rv[tid] = v2; ri[tid] = i2; }
            }
            __syncthreads();
        }
        if (tid == 0) { g_idxtop[bh * UU + t] = ri[0]; sv[ri[0]] = -INFINITY; }
        __syncthreads();
    }
}

// ---------------- mean(V) over L ----------------
__global__ void vmean_kernel() {
    int bh = blockIdx.x;
    int h = bh & (NH - 1), b = bh >> 3;
    int d = threadIdx.x;  // 64
    float s = 0.f;
    for (int l = 0; l < LL; l++)
        s += g_v[(((size_t)b * LL + l) * NH + h) * HD + d];
    g_vmean[bh * HD + d] = s * (1.0f / (float)LL);
}

// ---------------- broadcast vmean into attn buffer ----------------
__global__ void fill_kernel() {
    size_t i = (size_t)blockIdx.x * 256 + threadIdx.x;   // [b][l][h][d]
    int d = i & 63;
    int h = (i >> 6) & 7;
    int b = (int)(i >> 20);
    g_attn[i] = g_vmean[(b * NH + h) * HD + d];
}

// ---------------- full attention for the 24 selected queries per (b,h) ------------
__global__ void attnupd_kernel() {
    int bid = blockIdx.x;            // (b*NH+h)*UU + u
    int u = bid % UU;
    int bh = bid / UU;
    int h = bh & (NH - 1), b = bh >> 3;
    int tid = threadIdx.x;           // 256
    __shared__ float q[HD];
    __shared__ float p[LL];
    __shared__ float red[256];
    int qi = g_idxtop[bh * UU + u];
    if (tid < HD) q[tid] = g_q[(((size_t)b * LL + qi) * NH + h) * HD + tid];
    __syncthreads();
    float lmax = -INFINITY;
    for (int k = tid; k < LL; k += 256) {
        const float4* kr = (const float4*)(g_k + (((size_t)b * LL + k) * NH + h) * HD);
        float s = 0.f;
        #pragma unroll
        for (int d4 = 0; d4 < 16; d4++) {
            float4 kv = kr[d4];
            s += q[4*d4+0]*kv.x + q[4*d4+1]*kv.y + q[4*d4+2]*kv.z + q[4*d4+3]*kv.w;
        }
        s *= 0.125f;                   // / sqrt(64)
        p[k] = s;
        lmax = fmaxf(lmax, s);
    }
    red[tid] = lmax; __syncthreads();
    for (int s = 128; s > 0; s >>= 1) { if (tid < s) red[tid] = fmaxf(red[tid], red[tid+s]); __syncthreads(); }
    float mx = red[0]; __syncthreads();
    float lsum = 0.f;
    for (int k = tid; k < LL; k += 256) { float e = expf(p[k] - mx); p[k] = e; lsum += e; }
    red[tid] = lsum; __syncthreads();
    for (int s = 128; s > 0; s >>= 1) { if (tid < s) red[tid] += red[tid+s]; __syncthreads(); }
    float S = red[0]; __syncthreads();
    int d = tid & 63, part = tid >> 6;
    float acc = 0.f;
    for (int k = part; k < LL; k += 4)
        acc += p[k] * g_v[(((size_t)b * LL + k) * NH + h) * HD + d];
    red[tid] = acc; __syncthreads();
    if (tid < 64) {
        float tot = red[tid] + red[tid + 64] + red[tid + 128] + red[tid + 192];
        g_upd[(size_t)bid * HD + tid] = tot / S;
    }
}

// ---------------- scatter updated rows into attn buffer ----------------
__global__ void scatter_kernel() {
    int bid = blockIdx.x;     // 1536
    int u = bid % UU;
    int bh = bid / UU;
    int h = bh & (NH - 1), b = bh >> 3;
    int qi = g_idxtop[bh * UU + u];
    g_attn[(((size_t)b * LL + qi) * NH + h) * HD + threadIdx.x] =
        g_upd[(size_t)bid * HD + threadIdx.x];
}

// ---------------- layernorm over 512 (one block per row, strided variant) ---------
__global__ void ln512_kernel(const float* __restrict__ in, float* __restrict__ out,
                             const float* __restrict__ g, const float* __restrict__ b,
                             size_t strideIn, size_t strideOut) {
    int row = blockIdx.x;
    int tid = threadIdx.x;  // 128
    const float* x = in + (size_t)row * strideIn;
    float4 v = *(const float4*)(x + tid * 4);
    float s  = v.x + v.y + v.z + v.w;
    float ss = v.x*v.x + v.y*v.y + v.z*v.z + v.w*v.w;
    __shared__ float rs[4], rss[4];
    #pragma unroll
    for (int o = 16; o; o >>= 1) {
        s  += __shfl_xor_sync(~0u, s, o);
        ss += __shfl_xor_sync(~0u, ss, o);
    }
    int w = tid >> 5, lane = tid & 31;
    if (lane == 0) { rs[w] = s; rss[w] = ss; }
    __syncthreads();
    s  = rs[0] + rs[1] + rs[2] + rs[3];
    ss = rss[0] + rss[1] + rss[2] + rss[3];
    float m = s * (1.f / 512.f);
    float var = ss * (1.f / 512.f) - m * m;
    float r = rsqrtf(var + 1e-5f);
    float4 gg = *(const float4*)(g + tid * 4);
    float4 bb = *(const float4*)(b + tid * 4);
    float4 o4;
    o4.x = (v.x - m) * r * gg.x + bb.x;
    o4.y = (v.y - m) * r * gg.y + bb.y;
    o4.z = (v.z - m) * r * gg.z + bb.z;
    o4.w = (v.w - m) * r * gg.w + bb.w;
    *(float4*)(out + (size_t)row * strideOut + tid * 4) = o4;
}

// ---------------- final head: relu(last @ Wpre^T + bpre) @ Wfc^T + bfc ------------
__global__ void head_kernel(const float* __restrict__ Wpre, const float* __restrict__ bpre,
                            const float* __restrict__ Wfc,  const float* __restrict__ bfc,
                            float* __restrict__ out) {
    int b = blockIdx.x;
    int tid = threadIdx.x;  // 256
    __shared__ float red[256];
    const float* x = g_last + (size_t)b * DMODEL;
    float acc = bpre[tid];
    const float* w = Wpre + (size_t)tid * DMODEL;
    #pragma unroll 8
    for (int k = 0; k < DMODEL; k++) acc += x[k] * w[k];
    float pre = fmaxf(acc, 0.f);
    red[tid] = pre * Wfc[tid];
    __syncthreads();
    for (int s = 128; s > 0; s >>= 1) { if (tid < s) red[tid] += red[tid + s]; __syncthreads(); }
    if (tid == 0) out[b] = red[0] + bfc[0];
}

// ---------------- host orchestration ----------------
extern "C" void kernel_launch(void* const* d_in, const int* in_sizes, int n_in,
                              void* d_out, int out_size) {
    const float* x      = (const float*)d_in[0];
    const float* tfeat  = (const float*)d_in[1];
    const float* g_in   = (const float*)d_in[2];
    const float* b_in   = (const float*)d_in[3];
    const float* W_tok  = (const float*)d_in[4];
    const float* W_time = (const float*)d_in[5];
    const float* b_time = (const float*)d_in[6];
    const float* Wq     = (const float*)d_in[7];
    const float* bq     = (const float*)d_in[8];
    const float* Wk     = (const float*)d_in[9];
    const float* bk     = (const float*)d_in[10];
    const float* Wv     = (const float*)d_in[11];
    const float* bv     = (const float*)d_in[12];
    const float* Wo     = (const float*)d_in[13];
    const float* bo     = (const float*)d_in[14];
    const float* W1     = (const float*)d_in[15];
    const float* b1     = (const float*)d_in[16];
    const float* W2     = (const float*)d_in[17];
    const float* b2     = (const float*)d_in[18];
    const float* g1     = (const float*)d_in[19];
    const float* be1    = (const float*)d_in[20];
    const float* g2     = (const float*)d_in[21];
    const float* be2    = (const float*)d_in[22];
    const float* g_enc  = (const float*)d_in[23];
    const float* b_enc  = (const float*)d_in[24];
    const float* W_pre  = (const float*)d_in[25];
    const float* b_pre  = (const float*)d_in[26];
    const float* W_fc   = (const float*)d_in[27];
    const float* b_fc   = (const float*)d_in[28];

    float *h, *q, *k, *v, *attn, *ffn, *last;
    cudaGetSymbolAddress((void**)&h,    g_h);
    cudaGetSymbolAddress((void**)&q,    g_q);
    cudaGetSymbolAddress((void**)&k,    g_k);
    cudaGetSymbolAddress((void**)&v,    g_v);
    cudaGetSymbolAddress((void**)&attn, g_attn);
    cudaGetSymbolAddress((void**)&ffn,  g_ffn);
    cudaGetSymbolAddress((void**)&last, g_last);

    // 1) input LN + embedding
    ln32_kernel<<<MROWS / 8, 256>>>(x, g_in, b_in);
    embed_kernel<<<MROWS, 128>>>(tfeat, W_tok, W_time, b_time);

    dim3 gP(DMODEL / 128, MROWS / 128);   // N=512
    dim3 gF1(DFF / 128,  MROWS / 128);    // N=2048
    dim3 gF2(DMODEL / 128, MROWS / 128);  // N=512, K=2048

    for (int i = 0; i < NE; i++) {
        size_t wOff  = (size_t)i * DMODEL * DMODEL;
        size_t bOff  = (size_t)i * DMODEL;
        size_t w1Off = (size_t)i * DFF * DMODEL;
        size_t b1Off = (size_t)i * DFF;
        size_t w2Off = (size_t)i * DMODEL * DFF;

        sample_kernel<<<(LL * UU + 255) / 256, 256>>>(i);

        sgemm_kernel<0,0><<<gP, 256>>>(h, Wq + wOff, bq + bOff, nullptr, q, MROWS, DMODEL, DMODEL);
        sgemm_kernel<0,0><<<gP, 256>>>(h, Wk + wOff, bk + bOff, nullptr, k, MROWS, DMODEL, DMODEL);
        sgemm_kernel<0,0><<<gP, 256>>>(h, Wv + wOff, bv + bOff, nullptr, v, MROWS, DMODEL, DMODEL);

        mscore_kernel<<<(BB * NH * LL * 32) / 256, 256>>>();
        topk_kernel<<<BB * NH, 256>>>();
        vmean_kernel<<<BB * NH, HD>>>();
        fill_kernel<<<(MROWS * DMODEL) / 256, 256>>>();
        attnupd_kernel<<<BB * NH * UU, 256>>>();
        scatter_kernel<<<BB * NH * UU, HD>>>();

        sgemm_kernel<0,1><<<gP, 256>>>(attn, Wo + wOff, bo + bOff, h, h, MROWS, DMODEL, DMODEL);
        ln512_kernel<<<MROWS, 128>>>(h, h, g1 + bOff, be1 + bOff, DMODEL, DMODEL);

        sgemm_kernel<1,0><<<gF1, 256>>>(h, W1 + w1Off, b1 + b1Off, nullptr, ffn, MROWS, DFF, DMODEL);
        sgemm_kernel<0,1><<<gF2, 256>>>(ffn, W2 + w2Off, b2 + bOff, h, h, MROWS, DMODEL, DFF);
        ln512_kernel<<<MROWS, 128>>>(h, h, g2 + bOff, be2 + bOff, DMODEL, DMODEL);
    }

    // final encoder LN only needed for the last row of each batch
    ln512_kernel<<<BB, 128>>>(h + (size_t)(LL - 1) * DMODEL, last, g_enc, b_enc,
                              (size_t)LL * DMODEL, DMODEL);
    head_kernel<<<BB, 256>>>(W_pre, b_pre, W_fc, b_fc, (float*)d_out);
}

// round 5
// speedup vs baseline: 1.9008x; 1.9008x over previous
#include <cuda_runtime.h>
#include <cuda_bf16.h>
#include <math.h>
#include <stdint.h>
#include <stddef.h>

// ---------------- problem dims (fixed) ----------------
#define BB   8
#define LL   2048
#define CIN  32
#define DMODEL 512
#define DFF  2048
#define NH   8
#define HD   64
#define NE   2
#define UU   24
#define MROWS (BB*LL)      // 16384

// ---------------- scratch ----------------
__device__ float g_xln [MROWS*CIN];
__device__ float g_h   [(size_t)MROWS*DMODEL];
__device__ float g_q   [(size_t)MROWS*DMODEL];
__device__ float g_k   [(size_t)MROWS*DMODEL];
__device__ float g_v   [(size_t)MROWS*DMODEL];
__device__ float g_attn[(size_t)MROWS*DMODEL];
__device__ float g_ffn [(size_t)MROWS*DFF];
__device__ float g_M   [BB*NH*LL];
__device__ int   g_samp[LL*UU];
__device__ int   g_idxtop[BB*NH*UU];
__device__ float g_vmean[BB*NH*HD];
__device__ float g_upd [BB*NH*UU*HD];
__device__ float g_last[BB*DMODEL];

// ================= bf16 mma.sync helpers (sm_80-era PTX, valid on sm_103) ========
__device__ __forceinline__ void mma16816(float* c, const uint32_t* a, const uint32_t* b) {
    asm volatile(
        "mma.sync.aligned.m16n8k16.row.col.f32.bf16.bf16.f32 "
        "{%0,%1,%2,%3}, {%4,%5,%6,%7}, {%8,%9}, {%0,%1,%2,%3};"
        : "+f"(c[0]), "+f"(c[1]), "+f"(c[2]), "+f"(c[3])
        : "r"(a[0]), "r"(a[1]), "r"(a[2]), "r"(a[3]), "r"(b[0]), "r"(b[1]));
}
__device__ __forceinline__ void ldsm4(uint32_t& r0, uint32_t& r1, uint32_t& r2, uint32_t& r3,
                                      uint32_t addr) {
    asm volatile("ldmatrix.sync.aligned.m8n8.x4.shared.b16 {%0,%1,%2,%3}, [%4];"
                 : "=r"(r0), "=r"(r1), "=r"(r2), "=r"(r3) : "r"(addr));
}
__device__ __forceinline__ uint32_t packbf(__nv_bfloat16 a, __nv_bfloat16 b) {
    __nv_bfloat162 t = __halves2bfloat162(a, b);
    return *reinterpret_cast<uint32_t*>(&t);
}

// ================= bf16x3 tensor GEMM: C = A[M,K] @ W[N,K]^T + bias (+res)(relu) ==
// BM=BN=128, BK=32, 256 threads = 8 warps (2x4), warp tile 64x32.
// Row stride in smem: 40 bf16 (=80B) -> ldmatrix conflict-free.
#define RSTRIDE 10   // uint2 units per row (40 bf16)

template<int RELU, int RES>
__global__ __launch_bounds__(256, 2)
void tgemm_kernel(const float* __restrict__ A, const float* __restrict__ W,
                  const float* __restrict__ bias, const float* __restrict__ res,
                  float* __restrict__ C, int M, int N, int K) {
    __shared__ uint2 sA[2][128 * RSTRIDE];   // [hi/lo]
    __shared__ uint2 sB[2][128 * RSTRIDE];

    int tid = threadIdx.x;
    int wid = tid >> 5, lane = tid & 31;
    int warpM = wid >> 2, warpN = wid & 3;        // 2 x 4
    int bn = blockIdx.x, bm = blockIdx.y;

    const float* Ab = A + (size_t)(bm * 128) * K;
    const float* Wb = W + (size_t)(bn * 128) * K;

    float acc[4][4][4];
    #pragma unroll
    for (int mt = 0; mt < 4; mt++)
        #pragma unroll
        for (int nt = 0; nt < 4; nt++)
            #pragma unroll
            for (int e = 0; e < 4; e++) acc[mt][nt][e] = 0.f;

    uint32_t aBase[2], bBase[2];
    aBase[0] = (uint32_t)__cvta_generic_to_shared(&sA[0][0]);
    aBase[1] = (uint32_t)__cvta_generic_to_shared(&sA[1][0]);
    bBase[0] = (uint32_t)__cvta_generic_to_shared(&sB[0][0]);
    bBase[1] = (uint32_t)__cvta_generic_to_shared(&sB[1][0]);

    int ldc = tid & 7;          // float4 column (k sub-chunk)
    int ldr = tid >> 3;         // 0..31

    int nchunks = K >> 5;
    for (int c = 0; c < nchunks; c++) {
        int k0 = c * 32;
        // ---- load + split-convert A and W chunk into smem ----
        #pragma unroll
        for (int i = 0; i < 4; i++) {
            int row = ldr + 32 * i;
            float4 f = *(const float4*)(Ab + (size_t)row * K + k0 + ldc * 4);
            __nv_bfloat16 h0 = __float2bfloat16(f.x), h1 = __float2bfloat16(f.y);
            __nv_bfloat16 h2 = __float2bfloat16(f.z), h3 = __float2bfloat16(f.w);
            sA[0][row * RSTRIDE + ldc] = make_uint2(packbf(h0, h1), packbf(h2, h3));
            sA[1][row * RSTRIDE + ldc] = make_uint2(
                packbf(__float2bfloat16(f.x - __bfloat162float(h0)),
                       __float2bfloat16(f.y - __bfloat162float(h1))),
                packbf(__float2bfloat16(f.z - __bfloat162float(h2)),
                       __float2bfloat16(f.w - __bfloat162float(h3))));
            float4 g = *(const float4*)(Wb + (size_t)row * K + k0 + ldc * 4);
            __nv_bfloat16 w0 = __float2bfloat16(g.x), w1 = __float2bfloat16(g.y);
            __nv_bfloat16 w2 = __float2bfloat16(g.z), w3 = __float2bfloat16(g.w);
            sB[0][row * RSTRIDE + ldc] = make_uint2(packbf(w0, w1), packbf(w2, w3));
            sB[1][row * RSTRIDE + ldc] = make_uint2(
                packbf(__float2bfloat16(g.x - __bfloat162float(w0)),
                       __float2bfloat16(g.y - __bfloat162float(w1))),
                packbf(__float2bfloat16(g.z - __bfloat162float(w2)),
                       __float2bfloat16(g.w - __bfloat162float(w3))));
        }
        __syncthreads();

        // ---- 3 passes: Ah*Bh, Ah*Bl, Al*Bh ----
        #pragma unroll
        for (int pass = 0; pass < 3; pass++) {
            uint32_t aB = aBase[pass == 2];
            uint32_t bB = bBase[pass == 1];
            #pragma unroll
            for (int ks = 0; ks < 2; ks++) {
                int kb = ks * 32 + ((lane >> 4) << 4);   // bytes within row
                uint32_t afr[4][4];
                #pragma unroll
                for (int mt = 0; mt < 4; mt++) {
                    int row = warpM * 64 + mt * 16 + (lane & 15);
                    ldsm4(afr[mt][0], afr[mt][1], afr[mt][2], afr[mt][3],
                          aB + (uint32_t)(row * 80 + kb));
                }
                uint32_t bfr[4][2];
                #pragma unroll
                for (int p = 0; p < 2; p++) {
                    int row = warpN * 32 + p * 16 + (lane & 15);
                    uint32_t r0, r1, r2, r3;
                    ldsm4(r0, r1, r2, r3, bB + (uint32_t)(row * 80 + kb));
                    bfr[p*2][0] = r0; bfr[p*2+1][0] = r1;
                    bfr[p*2][1] = r2; bfr[p*2+1][1] = r3;
                }
                #pragma unroll
                for (int mt = 0; mt < 4; mt++)
                    #pragma unroll
                    for (int nt = 0; nt < 4; nt++)
                        mma16816(acc[mt][nt], afr[mt], bfr[nt]);
            }
        }
        __syncthreads();
    }

    // ---- epilogue: fragments -> global, fused bias/res/relu ----
    #pragma unroll
    for (int mt = 0; mt < 4; mt++) {
        int r0 = bm * 128 + warpM * 64 + mt * 16 + (lane >> 2);
        #pragma unroll
        for (int nt = 0; nt < 4; nt++) {
            int cc = bn * 128 + warpN * 32 + nt * 8 + (lane & 3) * 2;
            float2 bi = *(const float2*)(bias + cc);
            float2 o0 = make_float2(acc[mt][nt][0] + bi.x, acc[mt][nt][1] + bi.y);
            float2 o1 = make_float2(acc[mt][nt][2] + bi.x, acc[mt][nt][3] + bi.y);
            size_t g0 = (size_t)r0 * N + cc;
            size_t g1 = (size_t)(r0 + 8) * N + cc;
            if (RES) {
                float2 q0 = *(const float2*)(res + g0);
                float2 q1 = *(const float2*)(res + g1);
                o0.x += q0.x; o0.y += q0.y; o1.x += q1.x; o1.y += q1.y;
            }
            if (RELU) {
                o0.x = fmaxf(o0.x, 0.f); o0.y = fmaxf(o0.y, 0.f);
                o1.x = fmaxf(o1.x, 0.f); o1.y = fmaxf(o1.y, 0.f);
            }
            *(float2*)(C + g0) = o0;
            *(float2*)(C + g1) = o1;
        }
    }
}

// ---------------- threefry2x32 (matches JAX, partitionable) ----------------
__device__ __forceinline__ void tf2x32(uint32_t k0, uint32_t k1,
                                       uint32_t x0, uint32_t x1,
                                       uint32_t& o0, uint32_t& o1) {
    uint32_t ks2 = k0 ^ k1 ^ 0x1BD11BDAu;
    uint32_t v0 = x0 + k0, v1 = x1 + k1;
#define TF_RND(r) { v0 += v1; v1 = (v1 << (r)) | (v1 >> (32 - (r))); v1 ^= v0; }
    TF_RND(13) TF_RND(15) TF_RND(26) TF_RND(6)   v0 += k1;  v1 += ks2 + 1u;
    TF_RND(17) TF_RND(29) TF_RND(16) TF_RND(24)  v0 += ks2; v1 += k0 + 2u;
    TF_RND(13) TF_RND(15) TF_RND(26) TF_RND(6)   v0 += k0;  v1 += k1 + 3u;
    TF_RND(17) TF_RND(29) TF_RND(16) TF_RND(24)  v0 += k1;  v1 += ks2 + 4u;
    TF_RND(13) TF_RND(15) TF_RND(26) TF_RND(6)   v0 += ks2; v1 += k0 + 5u;
#undef TF_RND
    o0 = v0; o1 = v1;
}

__global__ void sample_kernel(int layer) {
    int j = blockIdx.x * blockDim.x + threadIdx.x;
    if (j >= LL * UU) return;
    uint32_t a0, a1;
    tf2x32(0u, 42u, 0u, (uint32_t)layer, a0, a1);   // fold_in
    uint32_t k2a, k2b;
    tf2x32(a0, a1, 0u, 1u, k2a, k2b);               // split -> second key
    uint32_t o0, o1;
    tf2x32(k2a, k2b, 0u, (uint32_t)j, o0, o1);      // partitionable random_bits
    g_samp[j] = (int)((o0 ^ o1) & 2047u);
}

// ---------------- input layernorm over C_IN=32 ----------------
__global__ void ln32_kernel(const float* __restrict__ x,
                            const float* __restrict__ g, const float* __restrict__ b) {
    int row  = blockIdx.x * 8 + (threadIdx.x >> 5);
    int lane = threadIdx.x & 31;
    float v = x[(size_t)row * CIN + lane];
    float s = v;
    #pragma unroll
    for (int o = 16; o; o >>= 1) s += __shfl_xor_sync(~0u, s, o);
    float m = s * (1.f / 32.f);
    float d = v - m;
    float ss = d * d;
    #pragma unroll
    for (int o = 16; o; o >>= 1) ss += __shfl_xor_sync(~0u, ss, o);
    float var = ss * (1.f / 32.f);
    float r = rsqrtf(var + 1e-5f);
    g_xln[(size_t)row * CIN + lane] = d * r * g[lane] + b[lane];
}

// ---------------- token conv + pos emb + time proj ----------------
__global__ void embed_kernel(const float* __restrict__ tfeat,
                             const float* __restrict__ Wtok,
                             const float* __restrict__ Wtime,
                             const float* __restrict__ btime) {
    int bl = blockIdx.x;
    int l = bl & (LL - 1);
    int b = bl >> 11;
    __shared__ float xs[96];
    __shared__ float tf[4];
    int tid = threadIdx.x; // 128
    if (tid < 96) {
        int w = tid / 32, c = tid % 32;
        int lsrc = (l - 1 + w + LL) & (LL - 1);
        xs[tid] = g_xln[((size_t)b * LL + lsrc) * CIN + c];
    }
    if (tid < 4) tf[tid] = tfeat[((size_t)b * LL + l) * 4 + tid];
    __syncthreads();
    for (int m = tid; m < DMODEL; m += 128) {
        float acc = btime[m];
        #pragma unroll 8
        for (int wc = 0; wc < 96; wc++) acc += xs[wc] * Wtok[wc * DMODEL + m];
        #pragma unroll
        for (int t = 0; t < 4; t++) acc += tf[t] * Wtime[m * 4 + t];
        int i2 = m & ~1;
        double dv  = exp(-(double)i2 * (9.210340371976184 / 512.0));
        double arg = (double)l * dv;
        float pe = (m & 1) ? (float)cos(arg) : (float)sin(arg);
        g_h[((size_t)b * LL + l) * DMODEL + m] = acc + pe;
    }
}

// ---------------- M scores ----------------
__global__ void mscore_kernel() {
    int wid  = (blockIdx.x * blockDim.x + threadIdx.x) >> 5;
    int lane = threadIdx.x & 31;
    if (wid >= BB * NH * LL) return;
    int l = wid & (LL - 1);
    int h = (wid >> 11) & (NH - 1);
    int b = wid >> 14;
    const float* qr = g_q + (((size_t)b * LL + l) * NH + h) * HD;
    float q0 = qr[lane * 2], q1 = qr[lane * 2 + 1];
    float mx = -INFINITY, sm = 0.f;
    #pragma unroll 4
    for (int s = 0; s < UU; s++) {
        int ks = g_samp[l * UU + s];
        const float* kr = g_k + (((size_t)b * LL + ks) * NH + h) * HD;
        float v = q0 * kr[lane * 2] + q1 * kr[lane * 2 + 1];
        #pragma unroll
        for (int o = 16; o; o >>= 1) v += __shfl_xor_sync(~0u, v, o);
        mx = fmaxf(mx, v);
        sm += v;
    }
    if (lane == 0)
        g_M[((size_t)(b * NH + h)) * LL + l] = mx - sm * (1.0f / (float)LL);
}

// ---------------- top-24 per (b,h), JAX tie semantics ----------------
__global__ void topk_kernel() {
    int bh = blockIdx.x;
    int tid = threadIdx.x;   // 256
    __shared__ float sv[LL];
    __shared__ float rv[256];
    __shared__ int   ri[256];
    for (int i = tid; i < LL; i += 256) sv[i] = g_M[(size_t)bh * LL + i];
    __syncthreads();
    for (int t = 0; t < UU; t++) {
        float bvv = -INFINITY; int bi = LL;
        for (int i = tid; i < LL; i += 256) {
            float v = sv[i];
            if (v > bvv || (v == bvv && i < bi)) { bvv = v; bi = i; }
        }
        rv[tid] = bvv; ri[tid] = bi;
        __syncthreads();
        for (int s = 128; s > 0; s >>= 1) {
            if (tid < s) {
                float v2 = rv[tid + s]; int i2 = ri[tid + s];
                if (v2 > rv[tid] || (v2 == rv[tid] && i2 < ri[tid])) { rv[tid] = v2; ri[tid] = i2; }
            }
            __syncthreads();
        }
        if (tid == 0) { g_idxtop[bh * UU + t] = ri[0]; sv[ri[0]] = -INFINITY; }
        __syncthreads();
    }
}

// ---------------- mean(V) over L ----------------
__global__ void vmean_kernel() {
    int bh = blockIdx.x;
    int h = bh & (NH - 1), b = bh >> 3;
    int d = threadIdx.x;  // 64
    float s = 0.f;
    for (int l = 0; l < LL; l++)
        s += g_v[(((size_t)b * LL + l) * NH + h) * HD + d];
    g_vmean[bh * HD + d] = s * (1.0f / (float)LL);
}

// ---------------- broadcast vmean ----------------
__global__ void fill_kernel() {
    size_t i = (size_t)blockIdx.x * 256 + threadIdx.x;
    int d = i & 63;
    int h = (i >> 6) & 7;
    int b = (int)(i >> 20);
    g_attn[i] = g_vmean[(b * NH + h) * HD + d];
}

// ---------------- full attention for 24 selected queries ----------------
__global__ void attnupd_kernel() {
    int bid = blockIdx.x;
    int u = bid % UU;
    int bh = bid / UU;
    int h = bh & (NH - 1), b = bh >> 3;
    int tid = threadIdx.x;           // 256
    __shared__ float q[HD];
    __shared__ float p[LL];
    __shared__ float red[256];
    int qi = g_idxtop[bh * UU + u];
    if (tid < HD) q[tid] = g_q[(((size_t)b * LL + qi) * NH + h) * HD + tid];
    __syncthreads();
    float lmax = -INFINITY;
    for (int k = tid; k < LL; k += 256) {
        const float4* kr = (const float4*)(g_k + (((size_t)b * LL + k) * NH + h) * HD);
        float s = 0.f;
        #pragma unroll
        for (int d4 = 0; d4 < 16; d4++) {
            float4 kv = kr[d4];
            s += q[4*d4+0]*kv.x + q[4*d4+1]*kv.y + q[4*d4+2]*kv.z + q[4*d4+3]*kv.w;
        }
        s *= 0.125f;
        p[k] = s;
        lmax = fmaxf(lmax, s);
    }
    red[tid] = lmax; __syncthreads();
    for (int s = 128; s > 0; s >>= 1) { if (tid < s) red[tid] = fmaxf(red[tid], red[tid+s]); __syncthreads(); }
    float mx = red[0]; __syncthreads();
    float lsum = 0.f;
    for (int k = tid; k < LL; k += 256) { float e = expf(p[k] - mx); p[k] = e; lsum += e; }
    red[tid] = lsum; __syncthreads();
    for (int s = 128; s > 0; s >>= 1) { if (tid < s) red[tid] += red[tid+s]; __syncthreads(); }
    float S = red[0]; __syncthreads();
    int d = tid & 63, part = tid >> 6;
    float acc = 0.f;
    for (int k = part; k < LL; k += 4)
        acc += p[k] * g_v[(((size_t)b * LL + k) * NH + h) * HD + d];
    red[tid] = acc; __syncthreads();
    if (tid < 64) {
        float tot = red[tid] + red[tid + 64] + red[tid + 128] + red[tid + 192];
        g_upd[(size_t)bid * HD + tid] = tot / S;
    }
}

// ---------------- scatter updated rows ----------------
__global__ void scatter_kernel() {
    int bid = blockIdx.x;
    int u = bid % UU;
    int bh = bid / UU;
    int h = bh & (NH - 1), b = bh >> 3;
    int qi = g_idxtop[bh * UU + u];
    g_attn[(((size_t)b * LL + qi) * NH + h) * HD + threadIdx.x] =
        g_upd[(size_t)bid * HD + threadIdx.x];
}

// ---------------- layernorm over 512 ----------------
__global__ void ln512_kernel(const float* __restrict__ in, float* __restrict__ out,
                             const float* __restrict__ g, const float* __restrict__ b,
                             size_t strideIn, size_t strideOut) {
    int row = blockIdx.x;
    int tid = threadIdx.x;  // 128
    const float* x = in + (size_t)row * strideIn;
    float4 v = *(const float4*)(x + tid * 4);
    float s  = v.x + v.y + v.z + v.w;
    float ss = v.x*v.x + v.y*v.y + v.z*v.z + v.w*v.w;
    __shared__ float rs[4], rss[4];
    #pragma unroll
    for (int o = 16; o; o >>= 1) {
        s  += __shfl_xor_sync(~0u, s, o);
        ss += __shfl_xor_sync(~0u, ss, o);
    }
    int w = tid >> 5, lane = tid & 31;
    if (lane == 0) { rs[w] = s; rss[w] = ss; }
    __syncthreads();
    s  = rs[0] + rs[1] + rs[2] + rs[3];
    ss = rss[0] + rss[1] + rss[2] + rss[3];
    float m = s * (1.f / 512.f);
    float var = ss * (1.f / 512.f) - m * m;
    float r = rsqrtf(var + 1e-5f);
    float4 gg = *(const float4*)(g + tid * 4);
    float4 bb = *(const float4*)(b + tid * 4);
    float4 o4;
    o4.x = (v.x - m) * r * gg.x + bb.x;
    o4.y = (v.y - m) * r * gg.y + bb.y;
    o4.z = (v.z - m) * r * gg.z + bb.z;
    o4.w = (v.w - m) * r * gg.w + bb.w;
    *(float4*)(out + (size_t)row * strideOut + tid * 4) = o4;
}

// ---------------- final head ----------------
__global__ void head_kernel(const float* __restrict__ Wpre, const float* __restrict__ bpre,
                            const float* __restrict__ Wfc,  const float* __restrict__ bfc,
                            float* __restrict__ out) {
    int b = blockIdx.x;
    int tid = threadIdx.x;  // 256
    __shared__ float red[256];
    const float* x = g_last + (size_t)b * DMODEL;
    float acc = bpre[tid];
    const float* w = Wpre + (size_t)tid * DMODEL;
    #pragma unroll 8
    for (int k = 0; k < DMODEL; k++) acc += x[k] * w[k];
    float pre = fmaxf(acc, 0.f);
    red[tid] = pre * Wfc[tid];
    __syncthreads();
    for (int s = 128; s > 0; s >>= 1) { if (tid < s) red[tid] += red[tid + s]; __syncthreads(); }
    if (tid == 0) out[b] = red[0] + bfc[0];
}

// ---------------- host orchestration ----------------
extern "C" void kernel_launch(void* const* d_in, const int* in_sizes, int n_in,
                              void* d_out, int out_size) {
    const float* x      = (const float*)d_in[0];
    const float* tfeat  = (const float*)d_in[1];
    const float* g_in   = (const float*)d_in[2];
    const float* b_in   = (const float*)d_in[3];
    const float* W_tok  = (const float*)d_in[4];
    const float* W_time = (const float*)d_in[5];
    const float* b_time = (const float*)d_in[6];
    const float* Wq     = (const float*)d_in[7];
    const float* bq     = (const float*)d_in[8];
    const float* Wk     = (const float*)d_in[9];
    const float* bk     = (const float*)d_in[10];
    const float* Wv     = (const float*)d_in[11];
    const float* bv     = (const float*)d_in[12];
    const float* Wo     = (const float*)d_in[13];
    const float* bo     = (const float*)d_in[14];
    const float* W1     = (const float*)d_in[15];
    const float* b1     = (const float*)d_in[16];
    const float* W2     = (const float*)d_in[17];
    const float* b2     = (const float*)d_in[18];
    const float* g1     = (const float*)d_in[19];
    const float* be1    = (const float*)d_in[20];
    const float* g2     = (const float*)d_in[21];
    const float* be2    = (const float*)d_in[22];
    const float* g_enc  = (const float*)d_in[23];
    const float* b_enc  = (const float*)d_in[24];
    const float* W_pre  = (const float*)d_in[25];
    const float* b_pre  = (const float*)d_in[26];
    const float* W_fc   = (const float*)d_in[27];
    const float* b_fc   = (const float*)d_in[28];

    float *h, *q, *k, *v, *attn, *ffn, *last;
    cudaGetSymbolAddress((void**)&h,    g_h);
    cudaGetSymbolAddress((void**)&q,    g_q);
    cudaGetSymbolAddress((void**)&k,    g_k);
    cudaGetSymbolAddress((void**)&v,    g_v);
    cudaGetSymbolAddress((void**)&attn, g_attn);
    cudaGetSymbolAddress((void**)&ffn,  g_ffn);
    cudaGetSymbolAddress((void**)&last, g_last);

    ln32_kernel<<<MROWS / 8, 256>>>(x, g_in, b_in);
    embed_kernel<<<MROWS, 128>>>(tfeat, W_tok, W_time, b_time);

    dim3 gP(DMODEL / 128, MROWS / 128);   // (4,128)
    dim3 gF1(DFF / 128,  MROWS / 128);    // (16,128)
    dim3 gF2(DMODEL / 128, MROWS / 128);  // (4,128), K=2048

    for (int i = 0; i < NE; i++) {
        size_t wOff  = (size_t)i * DMODEL * DMODEL;
        size_t bOff  = (size_t)i * DMODEL;
        size_t w1Off = (size_t)i * DFF * DMODEL;
        size_t b1Off = (size_t)i * DFF;
        size_t w2Off = (size_t)i * DMODEL * DFF;

        sample_kernel<<<(LL * UU + 255) / 256, 256>>>(i);

        tgemm_kernel<0,0><<<gP, 256>>>(h, Wq + wOff, bq + bOff, nullptr, q, MROWS, DMODEL, DMODEL);
        tgemm_kernel<0,0><<<gP, 256>>>(h, Wk + wOff, bk + bOff, nullptr, k, MROWS, DMODEL, DMODEL);
        tgemm_kernel<0,0><<<gP, 256>>>(h, Wv + wOff, bv + bOff, nullptr, v, MROWS, DMODEL, DMODEL);

        mscore_kernel<<<(BB * NH * LL * 32) / 256, 256>>>();
        topk_kernel<<<BB * NH, 256>>>();
        vmean_kernel<<<BB * NH, HD>>>();
        fill_kernel<<<(MROWS * DMODEL) / 256, 256>>>();
        attnupd_kernel<<<BB * NH * UU, 256>>>();
        scatter_kernel<<<BB * NH * UU, HD>>>();

        tgemm_kernel<0,1><<<gP, 256>>>(attn, Wo + wOff, bo + bOff, h, h, MROWS, DMODEL, DMODEL);
        ln512_kernel<<<MROWS, 128>>>(h, h, g1 + bOff, be1 + bOff, DMODEL, DMODEL);

        tgemm_kernel<1,0><<<gF1, 256>>>(h, W1 + w1Off, b1 + b1Off, nullptr, ffn, MROWS, DFF, DMODEL);
        tgemm_kernel<0,1><<<gF2, 256>>>(ffn, W2 + w2Off, b2 + bOff, h, h, MROWS, DMODEL, DFF);
        ln512_kernel<<<MROWS, 128>>>(h, h, g2 + bOff, be2 + bOff, DMODEL, DMODEL);
    }

    ln512_kernel<<<BB, 128>>>(h + (size_t)(LL - 1) * DMODEL, last, g_enc, b_enc,
                              (size_t)LL * DMODEL, DMODEL);
    head_kernel<<<BB, 256>>>(W_pre, b_pre, W_fc, b_fc, (float*)d_out);
}

// round 6
// speedup vs baseline: 1.9423x; 1.0218x over previous
#include <cuda_runtime.h>
#include <cuda_bf16.h>
#include <math.h>
#include <stdint.h>
#include <stddef.h>

// ---------------- problem dims (fixed) ----------------
#define BB   8
#define LL   2048
#define CIN  32
#define DMODEL 512
#define DFF  2048
#define NH   8
#define HD   64
#define NE   2
#define UU   24
#define MROWS (BB*LL)      // 16384

// ---------------- scratch ----------------
__device__ float g_xln [MROWS*CIN];
__device__ float g_h   [(size_t)MROWS*DMODEL];
__device__ float g_q   [(size_t)MROWS*DMODEL];
__device__ float g_k   [(size_t)MROWS*DMODEL];
__device__ float g_v   [(size_t)MROWS*DMODEL];
__device__ float g_M   [BB*NH*LL];
__device__ int   g_samp[LL*UU];
__device__ int   g_idxtop[BB*NH*UU];
__device__ float g_vmean[BB*NH*HD];
__device__ float g_upd [BB*NH*UU*HD];
__device__ float g_last[BB*DMODEL];
// bf16 hi/lo operand buffers
__device__ __nv_bfloat16 g_aHi[(size_t)MROWS*DMODEL];
__device__ __nv_bfloat16 g_aLo[(size_t)MROWS*DMODEL];
__device__ __nv_bfloat16 g_fHi[(size_t)MROWS*DFF];
__device__ __nv_bfloat16 g_fLo[(size_t)MROWS*DFF];
__device__ __nv_bfloat16 g_wHi[DFF*DMODEL];
__device__ __nv_bfloat16 g_wLo[DFF*DMODEL];

// ================= helpers =================
__device__ __forceinline__ uint32_t packbf(__nv_bfloat16 a, __nv_bfloat16 b) {
    __nv_bfloat162 t = __halves2bfloat162(a, b);
    return *reinterpret_cast<uint32_t*>(&t);
}
__device__ __forceinline__ void mma16816(float* c, const uint32_t* a, const uint32_t* b) {
    asm volatile(
        "mma.sync.aligned.m16n8k16.row.col.f32.bf16.bf16.f32 "
        "{%0,%1,%2,%3}, {%4,%5,%6,%7}, {%8,%9}, {%0,%1,%2,%3};"
        : "+f"(c[0]), "+f"(c[1]), "+f"(c[2]), "+f"(c[3])
        : "r"(a[0]), "r"(a[1]), "r"(a[2]), "r"(a[3]), "r"(b[0]), "r"(b[1]));
}
__device__ __forceinline__ void ldsm4(uint32_t& r0, uint32_t& r1, uint32_t& r2, uint32_t& r3,
                                      uint32_t addr) {
    asm volatile("ldmatrix.sync.aligned.m8n8.x4.shared.b16 {%0,%1,%2,%3}, [%4];"
                 : "=r"(r0), "=r"(r1), "=r"(r2), "=r"(r3) : "r"(addr));
}
#define CP_ASYNC16(dst, src) \
    asm volatile("cp.async.ca.shared.global [%0], [%1], 16;" :: "r"(dst), "l"(src))
#define CP_COMMIT() asm volatile("cp.async.commit_group;" ::: "memory")
#define CP_WAIT1()  asm volatile("cp.async.wait_group 1;" ::: "memory")
#define CP_WAIT0()  asm volatile("cp.async.wait_group 0;" ::: "memory")

// XOR-swizzled 64B-row tile: row r, 16B-chunk c -> r*64 + (c ^ ((r>>1)&3))*16
__device__ __forceinline__ void stage_tile(uint32_t dstBase, const __nv_bfloat16* src,
                                           int K, int k0, int tid) {
    int row = tid >> 2, c = tid & 3;
    #pragma unroll
    for (int i = 0; i < 2; i++) {
        int r = row + 64 * i;
        uint32_t doff = (uint32_t)(r * 64 + ((c ^ ((r >> 1) & 3)) << 4));
        CP_ASYNC16(dstBase + doff, src + (size_t)r * K + k0 + c * 8);
    }
}

// ================= pipelined bf16x3 tensor GEMM =================
// C = (Ah+Al)(Bh+Bl)^T approx: Ah*Bh + Ah*Bl + Al*Bh. BM=BN=128, BK=32.
// OUT=0: fp32 C (+bias,res,relu). OUT=1: bf16 hi/lo outputs only (+bias,relu).
template<int RELU, int RES, int OUT>
__global__ __launch_bounds__(256, 2)
void tgemm_kernel(const __nv_bfloat16* __restrict__ aHi, const __nv_bfloat16* __restrict__ aLo,
                  const __nv_bfloat16* __restrict__ bHi, const __nv_bfloat16* __restrict__ bLo,
                  const float* __restrict__ bias, const float* __restrict__ res,
                  float* __restrict__ C,
                  __nv_bfloat16* __restrict__ outHi, __nv_bfloat16* __restrict__ outLo,
                  int M, int N, int K) {
    extern __shared__ char smem[];
    uint32_t sb = (uint32_t)__cvta_generic_to_shared(smem);

    int tid = threadIdx.x;
    int wid = tid >> 5, lane = tid & 31;
    int warpM = wid >> 2, warpN = wid & 3;        // 2 x 4
    int bn = blockIdx.x, bm = blockIdx.y;

    const __nv_bfloat16* Ah = aHi + (size_t)(bm * 128) * K;
    const __nv_bfloat16* Al = aLo + (size_t)(bm * 128) * K;
    const __nv_bfloat16* Bh = bHi + (size_t)(bn * 128) * K;
    const __nv_bfloat16* Bl = bLo + (size_t)(bn * 128) * K;

    float acc[4][4][4];
    #pragma unroll
    for (int mt = 0; mt < 4; mt++)
        #pragma unroll
        for (int nt = 0; nt < 4; nt++)
            #pragma unroll
            for (int e = 0; e < 4; e++) acc[mt][nt][e] = 0.f;

    int nchunks = K >> 5;
    // prologue: stage 0
    {
        uint32_t s0 = sb;
        stage_tile(s0,         Ah, K, 0, tid);
        stage_tile(s0 + 8192,  Al, K, 0, tid);
        stage_tile(s0 + 16384, Bh, K, 0, tid);
        stage_tile(s0 + 24576, Bl, K, 0, tid);
        CP_COMMIT();
    }

    for (int c = 0; c < nchunks; c++) {
        if (c + 1 < nchunks) {
            uint32_t s1 = sb + ((c + 1) & 1) * 32768;
            int k0 = (c + 1) * 32;
            stage_tile(s1,         Ah, K, k0, tid);
            stage_tile(s1 + 8192,  Al, K, k0, tid);
            stage_tile(s1 + 16384, Bh, K, k0, tid);
            stage_tile(s1 + 24576, Bl, K, k0, tid);
            CP_COMMIT();
            CP_WAIT1();
        } else {
            CP_WAIT0();
        }
        __syncthreads();

        uint32_t st = sb + (c & 1) * 32768;
        #pragma unroll
        for (int pass = 0; pass < 3; pass++) {
            uint32_t aB = st + ((pass == 2) ? 8192 : 0);
            uint32_t bB = st + 16384 + ((pass == 1) ? 8192 : 0);
            #pragma unroll
            for (int ks = 0; ks < 2; ks++) {
                int cidx = ks * 2 + (lane >> 4);
                uint32_t afr[4][4];
                #pragma unroll
                for (int mt = 0; mt < 4; mt++) {
                    int row = warpM * 64 + mt * 16 + (lane & 15);
                    uint32_t addr = aB + row * 64 + ((cidx ^ ((row >> 1) & 3)) << 4);
                    ldsm4(afr[mt][0], afr[mt][1], afr[mt][2], afr[mt][3], addr);
                }
                uint32_t bfr[4][2];
                #pragma unroll
                for (int p = 0; p < 2; p++) {
                    int row = warpN * 32 + p * 16 + (lane & 15);
                    uint32_t addr = bB + row * 64 + ((cidx ^ ((row >> 1) & 3)) << 4);
                    uint32_t r0, r1, r2, r3;
                    ldsm4(r0, r1, r2, r3, addr);
                    bfr[p*2][0] = r0; bfr[p*2+1][0] = r1;
                    bfr[p*2][1] = r2; bfr[p*2+1][1] = r3;
                }
                #pragma unroll
                for (int mt = 0; mt < 4; mt++)
                    #pragma unroll
                    for (int nt = 0; nt < 4; nt++)
                        mma16816(acc[mt][nt], afr[mt], bfr[nt]);
            }
        }
        __syncthreads();
    }

    // ---- epilogue ----
    #pragma unroll
    for (int mt = 0; mt < 4; mt++) {
        int r0 = bm * 128 + warpM * 64 + mt * 16 + (lane >> 2);
        #pragma unroll
        for (int nt = 0; nt < 4; nt++) {
            int cc = bn * 128 + warpN * 32 + nt * 8 + (lane & 3) * 2;
            float2 bi = *(const float2*)(bias + cc);
            float2 o0 = make_float2(acc[mt][nt][0] + bi.x, acc[mt][nt][1] + bi.y);
            float2 o1 = make_float2(acc[mt][nt][2] + bi.x, acc[mt][nt][3] + bi.y);
            size_t g0 = (size_t)r0 * N + cc;
            size_t g1 = (size_t)(r0 + 8) * N + cc;
            if (RES) {
                float2 q0 = *(const float2*)(res + g0);
                float2 q1 = *(const float2*)(res + g1);
                o0.x += q0.x; o0.y += q0.y; o1.x += q1.x; o1.y += q1.y;
            }
            if (RELU) {
                o0.x = fmaxf(o0.x, 0.f); o0.y = fmaxf(o0.y, 0.f);
                o1.x = fmaxf(o1.x, 0.f); o1.y = fmaxf(o1.y, 0.f);
            }
            if (OUT == 0) {
                *(float2*)(C + g0) = o0;
                *(float2*)(C + g1) = o1;
            } else {
                __nv_bfloat16 h0 = __float2bfloat16(o0.x), h1 = __float2bfloat16(o0.y);
                __nv_bfloat16 h2 = __float2bfloat16(o1.x), h3 = __float2bfloat16(o1.y);
                *(uint32_t*)(outHi + g0) = packbf(h0, h1);
                *(uint32_t*)(outHi + g1) = packbf(h2, h3);
                *(uint32_t*)(outLo + g0) = packbf(
                    __float2bfloat16(o0.x - __bfloat162float(h0)),
                    __float2bfloat16(o0.y - __bfloat162float(h1)));
                *(uint32_t*)(outLo + g1) = packbf(
                    __float2bfloat16(o1.x - __bfloat162float(h2)),
                    __float2bfloat16(o1.y - __bfloat162float(h3)));
            }
        }
    }
}

// ---------------- fp32 -> bf16 hi/lo split (weights) ----------------
__global__ void convsplit_kernel(const float4* __restrict__ src,
                                 uint2* __restrict__ hi, uint2* __restrict__ lo, int n4) {
    int i = blockIdx.x * 256 + threadIdx.x;
    if (i >= n4) return;
    float4 f = src[i];
    __nv_bfloat16 h0 = __float2bfloat16(f.x), h1 = __float2bfloat16(f.y);
    __nv_bfloat16 h2 = __float2bfloat16(f.z), h3 = __float2bfloat16(f.w);
    hi[i] = make_uint2(packbf(h0, h1), packbf(h2, h3));
    lo[i] = make_uint2(
        packbf(__float2bfloat16(f.x - __bfloat162float(h0)),
               __float2bfloat16(f.y - __bfloat162float(h1))),
        packbf(__float2bfloat16(f.z - __bfloat162float(h2)),
               __float2bfloat16(f.w - __bfloat162float(h3))));
}

// ---------------- threefry2x32 (matches JAX, partitionable) ----------------
__device__ __forceinline__ void tf2x32(uint32_t k0, uint32_t k1,
                                       uint32_t x0, uint32_t x1,
                                       uint32_t& o0, uint32_t& o1) {
    uint32_t ks2 = k0 ^ k1 ^ 0x1BD11BDAu;
    uint32_t v0 = x0 + k0, v1 = x1 + k1;
#define TF_RND(r) { v0 += v1; v1 = (v1 << (r)) | (v1 >> (32 - (r))); v1 ^= v0; }
    TF_RND(13) TF_RND(15) TF_RND(26) TF_RND(6)   v0 += k1;  v1 += ks2 + 1u;
    TF_RND(17) TF_RND(29) TF_RND(16) TF_RND(24)  v0 += ks2; v1 += k0 + 2u;
    TF_RND(13) TF_RND(15) TF_RND(26) TF_RND(6)   v0 += k0;  v1 += k1 + 3u;
    TF_RND(17) TF_RND(29) TF_RND(16) TF_RND(24)  v0 += k1;  v1 += ks2 + 4u;
    TF_RND(13) TF_RND(15) TF_RND(26) TF_RND(6)   v0 += ks2; v1 += k0 + 5u;
#undef TF_RND
    o0 = v0; o1 = v1;
}

__global__ void sample_kernel(int layer) {
    int j = blockIdx.x * blockDim.x + threadIdx.x;
    if (j >= LL * UU) return;
    uint32_t a0, a1;
    tf2x32(0u, 42u, 0u, (uint32_t)layer, a0, a1);   // fold_in
    uint32_t k2a, k2b;
    tf2x32(a0, a1, 0u, 1u, k2a, k2b);               // split -> second key
    uint32_t o0, o1;
    tf2x32(k2a, k2b, 0u, (uint32_t)j, o0, o1);      // partitionable random_bits
    g_samp[j] = (int)((o0 ^ o1) & 2047u);
}

// ---------------- input layernorm over C_IN=32 ----------------
__global__ void ln32_kernel(const float* __restrict__ x,
                            const float* __restrict__ g, const float* __restrict__ b) {
    int row  = blockIdx.x * 8 + (threadIdx.x >> 5);
    int lane = threadIdx.x & 31;
    float v = x[(size_t)row * CIN + lane];
    float s = v;
    #pragma unroll
    for (int o = 16; o; o >>= 1) s += __shfl_xor_sync(~0u, s, o);
    float m = s * (1.f / 32.f);
    float d = v - m;
    float ss = d * d;
    #pragma unroll
    for (int o = 16; o; o >>= 1) ss += __shfl_xor_sync(~0u, ss, o);
    float var = ss * (1.f / 32.f);
    float r = rsqrtf(var + 1e-5f);
    g_xln[(size_t)row * CIN + lane] = d * r * g[lane] + b[lane];
}

// ---------------- token conv + pos emb + time proj (emits fp32 + hi/lo) -----------
__global__ void embed_kernel(const float* __restrict__ tfeat,
                             const float* __restrict__ Wtok,
                             const float* __restrict__ Wtime,
                             const float* __restrict__ btime) {
    int bl = blockIdx.x;
    int l = bl & (LL - 1);
    int b = bl >> 11;
    __shared__ float xs[96];
    __shared__ float tf[4];
    int tid = threadIdx.x; // 128
    if (tid < 96) {
        int w = tid / 32, c = tid % 32;
        int lsrc = (l - 1 + w + LL) & (LL - 1);
        xs[tid] = g_xln[((size_t)b * LL + lsrc) * CIN + c];
    }
    if (tid < 4) tf[tid] = tfeat[((size_t)b * LL + l) * 4 + tid];
    __syncthreads();
    for (int m = tid; m < DMODEL; m += 128) {
        float acc = btime[m];
        #pragma unroll 8
        for (int wc = 0; wc < 96; wc++) acc += xs[wc] * Wtok[wc * DMODEL + m];
        #pragma unroll
        for (int t = 0; t < 4; t++) acc += tf[t] * Wtime[m * 4 + t];
        int i2 = m & ~1;
        double dv  = exp(-(double)i2 * (9.210340371976184 / 512.0));
        double arg = (double)l * dv;
        float pe = (m & 1) ? (float)cos(arg) : (float)sin(arg);
        float v = acc + pe;
        size_t idx = ((size_t)b * LL + l) * DMODEL + m;
        g_h[idx] = v;
        __nv_bfloat16 hv = __float2bfloat16(v);
        g_aHi[idx] = hv;
        g_aLo[idx] = __float2bfloat16(v - __bfloat162float(hv));
    }
}

// ---------------- M scores ----------------
__global__ void mscore_kernel() {
    int wid  = (blockIdx.x * blockDim.x + threadIdx.x) >> 5;
    int lane = threadIdx.x & 31;
    if (wid >= BB * NH * LL) return;
    int l = wid & (LL - 1);
    int h = (wid >> 11) & (NH - 1);
    int b = wid >> 14;
    const float* qr = g_q + (((size_t)b * LL + l) * NH + h) * HD;
    float q0 = qr[lane * 2], q1 = qr[lane * 2 + 1];
    float mx = -INFINITY, sm = 0.f;
    #pragma unroll 4
    for (int s = 0; s < UU; s++) {
        int ks = g_samp[l * UU + s];
        const float* kr = g_k + (((size_t)b * LL + ks) * NH + h) * HD;
        float v = q0 * kr[lane * 2] + q1 * kr[lane * 2 + 1];
        #pragma unroll
        for (int o = 16; o; o >>= 1) v += __shfl_xor_sync(~0u, v, o);
        mx = fmaxf(mx, v);
        sm += v;
    }
    if (lane == 0)
        g_M[((size_t)(b * NH + h)) * LL + l] = mx - sm * (1.0f / (float)LL);
}

// ---------------- top-24 per (b,h), JAX tie semantics ----------------
__global__ void topk_kernel() {
    int bh = blockIdx.x;
    int tid = threadIdx.x;   // 256
    __shared__ float sv[LL];
    __shared__ float rv[256];
    __shared__ int   ri[256];
    for (int i = tid; i < LL; i += 256) sv[i] = g_M[(size_t)bh * LL + i];
    __syncthreads();
    for (int t = 0; t < UU; t++) {
        float bvv = -INFINITY; int bi = LL;
        for (int i = tid; i < LL; i += 256) {
            float v = sv[i];
            if (v > bvv || (v == bvv && i < bi)) { bvv = v; bi = i; }
        }
        rv[tid] = bvv; ri[tid] = bi;
        __syncthreads();
        for (int s = 128; s > 0; s >>= 1) {
            if (tid < s) {
                float v2 = rv[tid + s]; int i2 = ri[tid + s];
                if (v2 > rv[tid] || (v2 == rv[tid] && i2 < ri[tid])) { rv[tid] = v2; ri[tid] = i2; }
            }
            __syncthreads();
        }
        if (tid == 0) { g_idxtop[bh * UU + t] = ri[0]; sv[ri[0]] = -INFINITY; }
        __syncthreads();
    }
}

// ---------------- mean(V) over L (4-way parallel, deterministic) ----------------
__global__ void vmean_kernel() {
    int bh = blockIdx.x;
    int h = bh & (NH - 1), b = bh >> 3;
    int tid = threadIdx.x;            // 256
    int d = tid & 63, part = tid >> 6;
    float s = 0.f;
    for (int l = part; l < LL; l += 4)
        s += g_v[(((size_t)b * LL + l) * NH + h) * HD + d];
    __shared__ float red[256];
    red[tid] = s; __syncthreads();
    if (tid < 64) {
        float tot = red[tid] + red[tid + 64] + red[tid + 128] + red[tid + 192];
        g_vmean[bh * HD + tid] = tot * (1.0f / (float)LL);
    }
}

// ---------------- broadcast vmean into bf16 hi/lo attn buffer ----------------
__global__ void fill_kernel() {
    size_t i = (size_t)blockIdx.x * 256 + threadIdx.x;   // pair index over [b][l][h][d]
    size_t e = i * 2;
    int d = (int)(e & 63);
    int h = (int)((e >> 6) & 7);
    int b = (int)(e >> 20);
    float v0 = g_vmean[(b * NH + h) * HD + d];
    float v1 = g_vmean[(b * NH + h) * HD + d + 1];
    __nv_bfloat16 h0 = __float2bfloat16(v0), h1 = __float2bfloat16(v1);
    *(uint32_t*)(g_aHi + e) = packbf(h0, h1);
    *(uint32_t*)(g_aLo + e) = packbf(__float2bfloat16(v0 - __bfloat162float(h0)),
                                     __float2bfloat16(v1 - __bfloat162float(h1)));
}

// ---------------- full attention for 24 selected queries ----------------
__global__ void attnupd_kernel() {
    int bid = blockIdx.x;
    int u = bid % UU;
    int bh = bid / UU;
    int h = bh & (NH - 1), b = bh >> 3;
    int tid = threadIdx.x;           // 256
    __shared__ float q[HD];
    __shared__ float p[LL];
    __shared__ float red[256];
    int qi = g_idxtop[bh * UU + u];
    if (tid < HD) q[tid] = g_q[(((size_t)b * LL + qi) * NH + h) * HD + tid];
    __syncthreads();
    float lmax = -INFINITY;
    for (int k = tid; k < LL; k += 256) {
        const float4* kr = (const float4*)(g_k + (((size_t)b * LL + k) * NH + h) * HD);
        float s = 0.f;
        #pragma unroll
        for (int d4 = 0; d4 < 16; d4++) {
            float4 kv = kr[d4];
            s += q[4*d4+0]*kv.x + q[4*d4+1]*kv.y + q[4*d4+2]*kv.z + q[4*d4+3]*kv.w;
        }
        s *= 0.125f;
        p[k] = s;
        lmax = fmaxf(lmax, s);
    }
    red[tid] = lmax; __syncthreads();
    for (int s = 128; s > 0; s >>= 1) { if (tid < s) red[tid] = fmaxf(red[tid], red[tid+s]); __syncthreads(); }
    float mx = red[0]; __syncthreads();
    float lsum = 0.f;
    for (int k = tid; k < LL; k += 256) { float e = expf(p[k] - mx); p[k] = e; lsum += e; }
    red[tid] = lsum; __syncthreads();
    for (int s = 128; s > 0; s >>= 1) { if (tid < s) red[tid] += red[tid+s]; __syncthreads(); }
    float S = red[0]; __syncthreads();
    int d = tid & 63, part = tid >> 6;
    float acc = 0.f;
    for (int k = part; k < LL; k += 4)
        acc += p[k] * g_v[(((size_t)b * LL + k) * NH + h) * HD + d];
    red[tid] = acc; __syncthreads();
    if (tid < 64) {
        float tot = red[tid] + red[tid + 64] + red[tid + 128] + red[tid + 192];
        g_upd[(size_t)bid * HD + tid] = tot / S;
    }
}

// ---------------- scatter updated rows (bf16 hi/lo) ----------------
__global__ void scatter_kernel() {
    int bid = blockIdx.x;
    int u = bid % UU;
    int bh = bid / UU;
    int h = bh & (NH - 1), b = bh >> 3;
    int qi = g_idxtop[bh * UU + u];
    float v = g_upd[(size_t)bid * HD + threadIdx.x];
    size_t idx = (((size_t)b * LL + qi) * NH + h) * HD + threadIdx.x;
    __nv_bfloat16 hv = __float2bfloat16(v);
    g_aHi[idx] = hv;
    g_aLo[idx] = __float2bfloat16(v - __bfloat162float(hv));
}

// ---------------- layernorm over 512 (optionally emits hi/lo) ----------------
__global__ void ln512_kernel(const float* __restrict__ in, float* __restrict__ out,
                             const float* __restrict__ g, const float* __restrict__ b,
                             size_t strideIn, size_t strideOut,
                             __nv_bfloat16* __restrict__ hiOut,
                             __nv_bfloat16* __restrict__ loOut) {
    int row = blockIdx.x;
    int tid = threadIdx.x;  // 128
    const float* x = in + (size_t)row * strideIn;
    float4 v = *(const float4*)(x + tid * 4);
    float s  = v.x + v.y + v.z + v.w;
    float ss = v.x*v.x + v.y*v.y + v.z*v.z + v.w*v.w;
    __shared__ float rs[4], rss[4];
    #pragma unroll
    for (int o = 16; o; o >>= 1) {
        s  += __shfl_xor_sync(~0u, s, o);
        ss += __shfl_xor_sync(~0u, ss, o);
    }
    int w = tid >> 5, lane = tid & 31;
    if (lane == 0) { rs[w] = s; rss[w] = ss; }
    __syncthreads();
    s  = rs[0] + rs[1] + rs[2] + rs[3];
    ss = rss[0] + rss[1] + rss[2] + rss[3];
    float m = s * (1.f / 512.f);
    float var = ss * (1.f / 512.f) - m * m;
    float r = rsqrtf(var + 1e-5f);
    float4 gg = *(const float4*)(g + tid * 4);
    float4 bb = *(const float4*)(b + tid * 4);
    float4 o4;
    o4.x = (v.x - m) * r * gg.x + bb.x;
    o4.y = (v.y - m) * r * gg.y + bb.y;
    o4.z = (v.z - m) * r * gg.z + bb.z;
    o4.w = (v.w - m) * r * gg.w + bb.w;
    *(float4*)(out + (size_t)row * strideOut + tid * 4) = o4;
    if (hiOut) {
        size_t e = (size_t)row * DMODEL + tid * 4;
        __nv_bfloat16 h0 = __float2bfloat16(o4.x), h1 = __float2bfloat16(o4.y);
        __nv_bfloat16 h2 = __float2bfloat16(o4.z), h3 = __float2bfloat16(o4.w);
        *(uint2*)(hiOut + e) = make_uint2(packbf(h0, h1), packbf(h2, h3));
        *(uint2*)(loOut + e) = make_uint2(
            packbf(__float2bfloat16(o4.x - __bfloat162float(h0)),
                   __float2bfloat16(o4.y - __bfloat162float(h1))),
            packbf(__float2bfloat16(o4.z - __bfloat162float(h2)),
                   __float2bfloat16(o4.w - __bfloat162float(h3))));
    }
}

// ---------------- final head ----------------
__global__ void head_kernel(const float* __restrict__ Wpre, const float* __restrict__ bpre,
                            const float* __restrict__ Wfc,  const float* __restrict__ bfc,
                            float* __restrict__ out) {
    int b = blockIdx.x;
    int tid = threadIdx.x;  // 256
    __shared__ float red[256];
    const float* x = g_last + (size_t)b * DMODEL;
    float acc = bpre[tid];
    const float* w = Wpre + (size_t)tid * DMODEL;
    #pragma unroll 8
    for (int k = 0; k < DMODEL; k++) acc += x[k] * w[k];
    float pre = fmaxf(acc, 0.f);
    red[tid] = pre * Wfc[tid];
    __syncthreads();
    for (int s = 128; s > 0; s >>= 1) { if (tid < s) red[tid] += red[tid + s]; __syncthreads(); }
    if (tid == 0) out[b] = red[0] + bfc[0];
}

// ---------------- host orchestration ----------------
#define SMEM_GEMM 65536

extern "C" void kernel_launch(void* const* d_in, const int* in_sizes, int n_in,
                              void* d_out, int out_size) {
    const float* x      = (const float*)d_in[0];
    const float* tfeat  = (const float*)d_in[1];
    const float* g_in   = (const float*)d_in[2];
    const float* b_in   = (const float*)d_in[3];
    const float* W_tok  = (const float*)d_in[4];
    const float* W_time = (const float*)d_in[5];
    const float* b_time = (const float*)d_in[6];
    const float* Wq     = (const float*)d_in[7];
    const float* bq     = (const float*)d_in[8];
    const float* Wk     = (const float*)d_in[9];
    const float* bk     = (const float*)d_in[10];
    const float* Wv     = (const float*)d_in[11];
    const float* bv     = (const float*)d_in[12];
    const float* Wo     = (const float*)d_in[13];
    const float* bo     = (const float*)d_in[14];
    const float* W1     = (const float*)d_in[15];
    const float* b1     = (const float*)d_in[16];
    const float* W2     = (const float*)d_in[17];
    const float* b2     = (const float*)d_in[18];
    const float* g1     = (const float*)d_in[19];
    const float* be1    = (const float*)d_in[20];
    const float* g2     = (const float*)d_in[21];
    const float* be2    = (const float*)d_in[22];
    const float* g_enc  = (const float*)d_in[23];
    const float* b_enc  = (const float*)d_in[24];
    const float* W_pre  = (const float*)d_in[25];
    const float* b_pre  = (const float*)d_in[26];
    const float* W_fc   = (const float*)d_in[27];
    const float* b_fc   = (const float*)d_in[28];

    float *h, *q, *k, *v, *last;
    __nv_bfloat16 *aHi, *aLo, *fHi, *fLo, *wHi, *wLo;
    cudaGetSymbolAddress((void**)&h,    g_h);
    cudaGetSymbolAddress((void**)&q,    g_q);
    cudaGetSymbolAddress((void**)&k,    g_k);
    cudaGetSymbolAddress((void**)&v,    g_v);
    cudaGetSymbolAddress((void**)&last, g_last);
    cudaGetSymbolAddress((void**)&aHi,  g_aHi);
    cudaGetSymbolAddress((void**)&aLo,  g_aLo);
    cudaGetSymbolAddress((void**)&fHi,  g_fHi);
    cudaGetSymbolAddress((void**)&fLo,  g_fLo);
    cudaGetSymbolAddress((void**)&wHi,  g_wHi);
    cudaGetSymbolAddress((void**)&wLo,  g_wLo);

    cudaFuncSetAttribute(tgemm_kernel<0,0,0>, cudaFuncAttributeMaxDynamicSharedMemorySize, SMEM_GEMM);
    cudaFuncSetAttribute(tgemm_kernel<0,1,0>, cudaFuncAttributeMaxDynamicSharedMemorySize, SMEM_GEMM);
    cudaFuncSetAttribute(tgemm_kernel<1,0,1>, cudaFuncAttributeMaxDynamicSharedMemorySize, SMEM_GEMM);

    ln32_kernel<<<MROWS / 8, 256>>>(x, g_in, b_in);
    embed_kernel<<<MROWS, 128>>>(tfeat, W_tok, W_time, b_time);

    dim3 gP(DMODEL / 128, MROWS / 128);   // (4,128)
    dim3 gF1(DFF / 128,  MROWS / 128);    // (16,128)
    dim3 gF2(DMODEL / 128, MROWS / 128);  // (4,128), K=2048
    const int W512 = DMODEL * DMODEL / 4 / 256;   // convsplit blocks for 512x512
    const int W2048 = DFF * DMODEL / 4 / 256;     // for 2048x512 / 512x2048

    for (int i = 0; i < NE; i++) {
        size_t wOff  = (size_t)i * DMODEL * DMODEL;
        size_t bOff  = (size_t)i * DMODEL;
        size_t w1Off = (size_t)i * DFF * DMODEL;
        size_t b1Off = (size_t)i * DFF;
        size_t w2Off = (size_t)i * DMODEL * DFF;

        sample_kernel<<<(LL * UU + 255) / 256, 256>>>(i);

        convsplit_kernel<<<W512, 256>>>((const float4*)(Wq + wOff), (uint2*)wHi, (uint2*)wLo, DMODEL*DMODEL/4);
        tgemm_kernel<0,0,0><<<gP, 256, SMEM_GEMM>>>(aHi, aLo, wHi, wLo, bq + bOff, nullptr, q, nullptr, nullptr, MROWS, DMODEL, DMODEL);
        convsplit_kernel<<<W512, 256>>>((const float4*)(Wk + wOff), (uint2*)wHi, (uint2*)wLo, DMODEL*DMODEL/4);
        tgemm_kernel<0,0,0><<<gP, 256, SMEM_GEMM>>>(aHi, aLo, wHi, wLo, bk + bOff, nullptr, k, nullptr, nullptr, MROWS, DMODEL, DMODEL);
        convsplit_kernel<<<W512, 256>>>((const float4*)(Wv + wOff), (uint2*)wHi, (uint2*)wLo, DMODEL*DMODEL/4);
        tgemm_kernel<0,0,0><<<gP, 256, SMEM_GEMM>>>(aHi, aLo, wHi, wLo, bv + bOff, nullptr, v, nullptr, nullptr, MROWS, DMODEL, DMODEL);

        mscore_kernel<<<(BB * NH * LL * 32) / 256, 256>>>();
        topk_kernel<<<BB * NH, 256>>>();
        vmean_kernel<<<BB * NH, 256>>>();
        fill_kernel<<<(MROWS * DMODEL / 2) / 256, 256>>>();
        attnupd_kernel<<<BB * NH * UU, 256>>>();
        scatter_kernel<<<BB * NH * UU, HD>>>();

        convsplit_kernel<<<W512, 256>>>((const float4*)(Wo + wOff), (uint2*)wHi, (uint2*)wLo, DMODEL*DMODEL/4);
        tgemm_kernel<0,1,0><<<gP, 256, SMEM_GEMM>>>(aHi, aLo, wHi, wLo, bo + bOff, h, h, nullptr, nullptr, MROWS, DMODEL, DMODEL);
        ln512_kernel<<<MROWS, 128>>>(h, h, g1 + bOff, be1 + bOff, DMODEL, DMODEL, aHi, aLo);

        convsplit_kernel<<<W2048, 256>>>((const float4*)(W1 + w1Off), (uint2*)wHi, (uint2*)wLo, DFF*DMODEL/4);
        tgemm_kernel<1,0,1><<<gF1, 256, SMEM_GEMM>>>(aHi, aLo, wHi, wLo, b1 + b1Off, nullptr, nullptr, fHi, fLo, MROWS, DFF, DMODEL);
        convsplit_kernel<<<W2048, 256>>>((const float4*)(W2 + w2Off), (uint2*)wHi, (uint2*)wLo, DMODEL*DFF/4);
        tgemm_kernel<0,1,0><<<gF2, 256, SMEM_GEMM>>>(fHi, fLo, wHi, wLo, b2 + bOff, h, h, nullptr, nullptr, MROWS, DMODEL, DFF);
        ln512_kernel<<<MROWS, 128>>>(h, h, g2 + bOff, be2 + bOff, DMODEL, DMODEL, aHi, aLo);
    }

    ln512_kernel<<<BB, 128>>>(h + (size_t)(LL - 1) * DMODEL, last, g_enc, b_enc,
                              (size_t)LL * DMODEL, DMODEL, nullptr, nullptr);
    head_kernel<<<BB, 256>>>(W_pre, b_pre, W_fc, b_fc, (float*)d_out);
}